// round 2
// baseline (speedup 1.0000x reference)
#include <cuda_runtime.h>
#include <cuda_bf16.h>

// RWKV WKV recurrence:
//   a_t = exp(w_t)*a_{t-1} + exp(k_t)
//   b_t = exp(w_t)*b_{t-1} + exp(k_t)*v_t
//   out_t = b_t / a_t
// Shapes: k,v,w,out = [B=16, T=2048, D=1024] fp32.
// One thread per (b,d) chain; lane index = d -> fully coalesced 128B warp lines.
// Double-buffered register prefetch of U timesteps to build MLP (~48 LDGs in
// flight per warp) since we only have ~3.5 warps/SM.

#define BB 16
#define TT 2048
#define DD 1024
#define U  16

__global__ __launch_bounds__(128, 1)
void wkv_kernel(const float* __restrict__ K,
                const float* __restrict__ V,
                const float* __restrict__ W,
                float* __restrict__ O) {
    int idx = blockIdx.x * blockDim.x + threadIdx.x;   // chain id in [0, B*D)
    int b = idx >> 10;          // / DD
    int d = idx & (DD - 1);     // % DD

    size_t base = (size_t)b * TT * DD + d;
    const float* kp = K + base;
    const float* vp = V + base;
    const float* wp = W + base;
    float*       op = O + base;

    float a = 0.0f;
    float s = 0.0f;

    float k0[U], v0[U], w0[U];
    float k1[U], v1[U], w1[U];

    // Prime first block
#pragma unroll
    for (int u = 0; u < U; u++) {
        size_t off = (size_t)u * DD;
        k0[u] = kp[off];
        v0[u] = vp[off];
        w0[u] = wp[off];
    }

    for (int t = 0; t < TT; t += U) {
        // Prefetch next block while computing current (keeps ~3*U LDGs in flight)
        if (t + U < TT) {
#pragma unroll
            for (int u = 0; u < U; u++) {
                size_t off = (size_t)(t + U + u) * DD;
                k1[u] = kp[off];
                v1[u] = vp[off];
                w1[u] = wp[off];
            }
        }

#pragma unroll
        for (int u = 0; u < U; u++) {
            float ek = __expf(k0[u]);
            float ew = __expf(w0[u]);
            a = fmaf(ew, a, ek);
            s = fmaf(ew, s, ek * v0[u]);
            op[(size_t)(t + u) * DD] = __fdividef(s, a);
        }

#pragma unroll
        for (int u = 0; u < U; u++) {
            k0[u] = k1[u];
            v0[u] = v1[u];
            w0[u] = w1[u];
        }
    }
}

extern "C" void kernel_launch(void* const* d_in, const int* in_sizes, int n_in,
                              void* d_out, int out_size) {
    const float* k = (const float*)d_in[0];
    const float* v = (const float*)d_in[1];
    const float* w = (const float*)d_in[2];
    float* out = (float*)d_out;

    int chains = BB * DD;              // 16384
    int block = 128;
    int grid = chains / block;         // 128
    wkv_kernel<<<grid, block>>>(k, v, w, out);
}